// round 9
// baseline (speedup 1.0000x reference)
#include <cuda_runtime.h>
#include <cstdint>
#include <math.h>

// Problem constants (fixed by the reference)
#define B_      8
#define HQ_     32
#define HK_     8
#define D_      64
#define S_      32
#define NB_     128
#define W_      1024
#define G_      (HQ_ / HK_)     // 4 q heads per kv head

#define NSPLIT  16
#define NWARPS  4
#define NTHREADS (NWARPS * 32)

// float4-unit strides in the cache [P, 2, Hk, S, D]:
#define PG4   8192      // 2*HK*S*D/4
#define HK4   512       // S*D/4
#define VP4   4096      // HK*S*D/4

// Split-KV scratch (no cudaMalloc allowed)
__device__ float g_l[B_ * HQ_ * NSPLIT];
__device__ float g_acc[B_ * HQ_ * NSPLIT * D_];
__device__ int   g_cnt[B_ * HK_];                 // zero-init; self-resetting

__device__ __forceinline__ float dot8(float4 qa, float4 qb, float4 ka, float4 kb)
{
    return qa.x*ka.x + qa.y*ka.y + qa.z*ka.z + qa.w*ka.w
         + qb.x*kb.x + qb.y*kb.y + qb.z*kb.z + qb.w*kb.w;
}

__global__ __launch_bounds__(NTHREADS)
void attn_fused_kernel(const float* __restrict__ q_last,
                       const float* __restrict__ k_last,
                       const float* __restrict__ v_last,
                       const float* __restrict__ cache,
                       const int*   __restrict__ block_ids,
                       const int*   __restrict__ start_pos,
                       const float* __restrict__ sink,
                       float*       __restrict__ out)
{
    const int b     = blockIdx.x;
    const int hk    = blockIdx.y;
    const int split = blockIdx.z;
    const int tid   = threadIdx.x;
    const int w     = tid >> 5;
    const int lane  = tid & 31;
    const int e     = lane & 7;        // 8 lanes cover a D=64 row (2x float4)
    const int q4    = lane >> 3;       // quad id within warp

    const int pos = start_pos[b];
    const int t0  = max(0, pos - W_ + 1);
    const int L   = pos - t0 + 1;
    const int chunk = (L + NSPLIT - 1) / NSPLIT;   // <= 64
    const int ts  = t0 + split * chunk;
    const int te  = min(ts + chunk, pos + 1);
    const int te2 = min(te, pos);      // main loop excludes t == pos

    const float4* cache4 = (const float4*)cache;
    const int*    bid    = block_ids + b * NB_;

    // chunk <= 64 positions spans at most 3 pages: preload ids into regs
    const int bp = ts >> 5;
    const int p0 = bid[min(bp + 0, NB_ - 1)];
    const int p1 = bid[min(bp + 1, NB_ - 1)];
    const int p2 = bid[min(bp + 2, NB_ - 1)];

    // q lives in shared memory (CTA-uniform), pre-scaled by 1/sqrt(64).
    // Layout: sq[g][i], i = float4 slice 0..15 of the D=64 row.
    __shared__ float4 sq[G_][16];
    if (tid < G_ * 16) {
        const int g = tid >> 4;
        const int i = tid & 15;
        const float4 v = ((const float4*)(q_last +
                        ((size_t)(b * HQ_ + hk * G_ + g)) * D_))[i];
        sq[g][i] = make_float4(v.x*0.125f, v.y*0.125f, v.z*0.125f, v.w*0.125f);
    }
    __syncthreads();

    float  l[G_];
    float4 acca[G_], accb[G_];
#pragma unroll
    for (int g = 0; g < G_; g++) {
        l[g] = 0.f;
        acca[g] = make_float4(0.f,0.f,0.f,0.f);
        accb[g] = make_float4(0.f,0.f,0.f,0.f);
    }

    const int khk = hk * HK4;

    // ---- main loop: 8 positions per warp-iteration, all loads front-batched ----
    for (int wb = ts + (w << 3); wb < te2; wb += NWARPS * 8) {
        const int tA = wb + q4;            // quad A positions
        const int tB = wb + 4 + q4;        // quad B positions
        const bool vA = tA < te2;
        const bool vB = tB < te2;
        const int tcA = vA ? tA : (te2 - 1);
        const int tcB = vB ? tB : (te2 - 1);
        const int jA = (tcA >> 5) - bp;
        const int jB = (tcB >> 5) - bp;
        const int pgA = (jA == 0) ? p0 : ((jA == 1) ? p1 : p2);
        const int pgB = (jB == 0) ? p0 : ((jB == 1) ? p1 : p2);
        const int iA = pgA * PG4 + khk + (tcA & 31) * 16 + e;
        const int iB = pgB * PG4 + khk + (tcB & 31) * 16 + e;

        // 8 independent LDG.128 per lane
        const float4 kaA = cache4[iA],       kbA = cache4[iA + 8];
        const float4 vaA = cache4[iA + VP4], vbA = cache4[iA + VP4 + 8];
        const float4 kaB = cache4[iB],       kbB = cache4[iB + 8];
        const float4 vaB = cache4[iB + VP4], vbB = cache4[iB + VP4 + 8];

        float sA[G_], sB[G_];
#pragma unroll
        for (int g = 0; g < G_; g++) {
            const float4 qa = sq[g][e];
            const float4 qb = sq[g][e + 8];
            sA[g] = dot8(qa, qb, kaA, kbA);
            sB[g] = dot8(qa, qb, kaB, kbB);
        }
#pragma unroll
        for (int off = 4; off >= 1; off >>= 1) {
#pragma unroll
            for (int g = 0; g < G_; g++) {
                sA[g] += __shfl_xor_sync(0xffffffffu, sA[g], off);
                sB[g] += __shfl_xor_sync(0xffffffffu, sB[g], off);
            }
        }
#pragma unroll
        for (int g = 0; g < G_; g++) {
            const float pA = vA ? __expf(sA[g]) : 0.f;
            const float pB = vB ? __expf(sB[g]) : 0.f;
            l[g] += pA + pB;
            acca[g].x += pA * vaA.x + pB * vaB.x;
            acca[g].y += pA * vaA.y + pB * vaB.y;
            acca[g].z += pA * vaA.z + pB * vaB.z;
            acca[g].w += pA * vaA.w + pB * vaB.w;
            accb[g].x += pA * vbA.x + pB * vbB.x;
            accb[g].y += pA * vbA.y + pB * vbB.y;
            accb[g].z += pA * vbA.z + pB * vbB.z;
            accb[g].w += pA * vbA.w + pB * vbB.w;
        }
    }

    // ---- t == pos handled once, by warp 0 / lane-group 0 of the owning split ----
    if (pos >= ts && pos < te && w == 0 && lane < 8) {
        const float4* kr = (const float4*)(k_last + ((size_t)(b * HK_ + hk)) * D_);
        const float4* vr = (const float4*)(v_last + ((size_t)(b * HK_ + hk)) * D_);
        const float4 ka = kr[e], kb = kr[e + 8];
        const float4 va = vr[e], vb = vr[e + 8];
        float s[G_];
#pragma unroll
        for (int g = 0; g < G_; g++)
            s[g] = dot8(sq[g][e], sq[g][e + 8], ka, kb);
#pragma unroll
        for (int off = 4; off >= 1; off >>= 1) {
#pragma unroll
            for (int g = 0; g < G_; g++)
                s[g] += __shfl_xor_sync(0x000000ffu, s[g], off);
        }
#pragma unroll
        for (int g = 0; g < G_; g++) {
            const float p = __expf(s[g]);
            l[g] += p;
            acca[g].x += p * va.x; acca[g].y += p * va.y;
            acca[g].z += p * va.z; acca[g].w += p * va.w;
            accb[g].x += p * vb.x; accb[g].y += p * vb.y;
            accb[g].z += p * vb.z; accb[g].w += p * vb.w;
        }
    }

    // ---- merge the 4 lane-groups of each warp (pure sums, no max) ----
#pragma unroll
    for (int g = 0; g < G_; g++) {
#pragma unroll
        for (int off = 8; off <= 16; off <<= 1) {
            l[g]      += __shfl_xor_sync(0xffffffffu, l[g], off);
            acca[g].x += __shfl_xor_sync(0xffffffffu, acca[g].x, off);
            acca[g].y += __shfl_xor_sync(0xffffffffu, acca[g].y, off);
            acca[g].z += __shfl_xor_sync(0xffffffffu, acca[g].z, off);
            acca[g].w += __shfl_xor_sync(0xffffffffu, acca[g].w, off);
            accb[g].x += __shfl_xor_sync(0xffffffffu, accb[g].x, off);
            accb[g].y += __shfl_xor_sync(0xffffffffu, accb[g].y, off);
            accb[g].z += __shfl_xor_sync(0xffffffffu, accb[g].z, off);
            accb[g].w += __shfl_xor_sync(0xffffffffu, accb[g].w, off);
        }
    }

    // ---- cross-warp combine via smem ----
    __shared__ float sl_[NWARPS][G_];
    __shared__ float sa_[NWARPS][G_][D_];
    if (lane < 8) {
#pragma unroll
        for (int g = 0; g < G_; g++) {
            ((float4*)sa_[w][g])[e]     = acca[g];
            ((float4*)sa_[w][g])[e + 8] = accb[g];
        }
    }
    if (lane == 0) {
#pragma unroll
        for (int g = 0; g < G_; g++) sl_[w][g] = l[g];
    }
    __syncthreads();

#pragma unroll
    for (int rep = 0; rep < 2; rep++) {
        const int i = tid + rep * NTHREADS;        // 0..255 -> (g,d)
        const int g = i >> 6;
        const int d = i & 63;
        float Lt = 0.f, A = 0.f;
#pragma unroll
        for (int ww = 0; ww < NWARPS; ww++) {
            Lt += sl_[ww][g];
            A  += sa_[ww][g][d];
        }
        const int idx = ((b * HK_ + hk) * G_ + g) * NSPLIT + split;
        if (d == 0) g_l[idx] = Lt;
        g_acc[idx * D_ + d] = A;
    }

    // ---- split-KV finalization: last CTA per (b,hk) reduces ----
    __shared__ int is_last;
    __threadfence();
    __syncthreads();
    if (tid == 0) {
        const int old = atomicAdd(&g_cnt[b * HK_ + hk], 1);
        is_last = (old == NSPLIT - 1);
    }
    __syncthreads();
    if (!is_last) return;
    __threadfence();

#pragma unroll
    for (int rep = 0; rep < 2; rep++) {
        const int i = tid + rep * NTHREADS;
        const int g = i >> 6;
        const int d = i & 63;
        const int hq = hk * G_ + g;
        const int base = ((b * HK_ + hk) * G_ + g) * NSPLIT;

        float Lt = __expf(sink[hq]);               // sink mass, denominator only
        float A  = 0.f;
#pragma unroll
        for (int s = 0; s < NSPLIT; s++) {
            Lt += g_l[base + s];
            A  += g_acc[(base + s) * D_ + d];
        }
        out[((size_t)(b * HQ_ + hq)) * D_ + d] = A / Lt;
    }
    if (tid == 0) g_cnt[b * HK_ + hk] = 0;         // reset for next graph replay
}

extern "C" void kernel_launch(void* const* d_in, const int* in_sizes, int n_in,
                              void* d_out, int out_size)
{
    const float* q_last     = (const float*)d_in[0];
    const float* k_last     = (const float*)d_in[1];
    const float* v_last     = (const float*)d_in[2];
    const float* cache      = (const float*)d_in[3];
    const int*   block_ids  = (const int*)d_in[4];
    const int*   start_pos  = (const int*)d_in[5];
    const float* sink       = (const float*)d_in[6];
    float*       out        = (float*)d_out;

    dim3 grid(B_, HK_, NSPLIT);
    attn_fused_kernel<<<grid, NTHREADS>>>(q_last, k_last, v_last, cache,
                                          block_ids, start_pos, sink, out);
}

// round 10
// speedup vs baseline: 1.2400x; 1.2400x over previous
#include <cuda_runtime.h>
#include <cstdint>
#include <math.h>

// Problem constants (fixed by the reference)
#define B_      8
#define HQ_     32
#define HK_     8
#define D_      64
#define S_      32
#define NB_     128
#define W_      1024
#define G_      (HQ_ / HK_)     // 4 q heads per kv head

#define GC      2               // heads handled per CTA (G_ / 2)
#define NSPLIT  8
#define NWARPS  4
#define NTHREADS (NWARPS * 32)

// float4-unit strides in the cache [P, 2, Hk, S, D]:
#define PG4   8192      // 2*HK*S*D/4
#define HK4   512       // S*D/4
#define VP4   4096      // HK*S*D/4

// Split-KV scratch (no cudaMalloc allowed)
// idx = (b*HQ + hq)*NSPLIT + split
__device__ float g_l[B_ * HQ_ * NSPLIT];
__device__ float g_acc[B_ * HQ_ * NSPLIT * D_];
__device__ int   g_cnt[B_ * HK_ * 2];             // per (b, hk-half); self-resetting

__device__ __forceinline__ float dot8(float4 qa, float4 qb, float4 ka, float4 kb)
{
    return qa.x*ka.x + qa.y*ka.y + qa.z*ka.z + qa.w*ka.w
         + qb.x*kb.x + qb.y*kb.y + qb.z*kb.z + qb.w*kb.w;
}

__global__ __launch_bounds__(NTHREADS)
void attn_fused_kernel(const float* __restrict__ q_last,
                       const float* __restrict__ k_last,
                       const float* __restrict__ v_last,
                       const float* __restrict__ cache,
                       const int*   __restrict__ block_ids,
                       const int*   __restrict__ start_pos,
                       const float* __restrict__ sink,
                       float*       __restrict__ out)
{
    const int b     = blockIdx.x;
    const int hk2   = blockIdx.y;      // 0..15: (hk, head-half)
    const int hk    = hk2 >> 1;
    const int gh    = (hk2 & 1) * GC;  // first grouped head of this CTA
    const int split = blockIdx.z;
    const int tid   = threadIdx.x;
    const int w     = tid >> 5;
    const int lane  = tid & 31;
    const int e     = lane & 7;        // 8 lanes cover a D=64 row (2x float4)
    const int q4    = lane >> 3;       // quad id within warp

    const int pos = start_pos[b];
    const int t0  = max(0, pos - W_ + 1);
    const int L   = pos - t0 + 1;
    const int chunk = (L + NSPLIT - 1) / NSPLIT;   // <= 128
    const int ts  = t0 + split * chunk;
    const int te  = min(ts + chunk, pos + 1);
    const int te2 = min(te, pos);      // main loop excludes t == pos

    const float4* cache4 = (const float4*)cache;
    const int*    bid    = block_ids + b * NB_;

    // chunk <= 128 positions spans at most 5 pages: preload ids into regs
    const int bp = ts >> 5;
    const int p0 = bid[min(bp + 0, NB_ - 1)];
    const int p1 = bid[min(bp + 1, NB_ - 1)];
    const int p2 = bid[min(bp + 2, NB_ - 1)];
    const int p3 = bid[min(bp + 3, NB_ - 1)];
    const int p4 = bid[min(bp + 4, NB_ - 1)];

    // q for this CTA's GC heads, pre-scaled by 1/sqrt(64)
    float4 qa[GC], qb[GC];
#pragma unroll
    for (int g = 0; g < GC; g++) {
        const float4* qr = (const float4*)(q_last +
                          ((size_t)(b * HQ_ + hk * G_ + gh + g)) * D_);
        float4 a = qr[e], bb = qr[e + 8];
        qa[g] = make_float4(a.x*0.125f,  a.y*0.125f,  a.z*0.125f,  a.w*0.125f);
        qb[g] = make_float4(bb.x*0.125f, bb.y*0.125f, bb.z*0.125f, bb.w*0.125f);
    }

    float  l[GC];
    float4 acca[GC], accb[GC];
#pragma unroll
    for (int g = 0; g < GC; g++) {
        l[g] = 0.f;
        acca[g] = make_float4(0.f,0.f,0.f,0.f);
        accb[g] = make_float4(0.f,0.f,0.f,0.f);
    }

    const int khk = hk * HK4;

    // ---- main loop: 8 positions per warp-iteration, all loads front-batched ----
    for (int wb = ts + (w << 3); wb < te2; wb += NWARPS * 8) {
        const int tA = wb + q4;            // quad A positions
        const int tB = wb + 4 + q4;        // quad B positions
        const bool vA = tA < te2;
        const bool vB = tB < te2;
        const int tcA = vA ? tA : (te2 - 1);
        const int tcB = vB ? tB : (te2 - 1);
        const int jA = (tcA >> 5) - bp;
        const int jB = (tcB >> 5) - bp;
        const int pgA = (jA == 0) ? p0 : (jA == 1) ? p1 : (jA == 2) ? p2
                      : (jA == 3) ? p3 : p4;
        const int pgB = (jB == 0) ? p0 : (jB == 1) ? p1 : (jB == 2) ? p2
                      : (jB == 3) ? p3 : p4;
        const int iA = pgA * PG4 + khk + (tcA & 31) * 16 + e;
        const int iB = pgB * PG4 + khk + (tcB & 31) * 16 + e;

        // 8 independent LDG.128 per lane
        const float4 kaA = cache4[iA],       kbA = cache4[iA + 8];
        const float4 vaA = cache4[iA + VP4], vbA = cache4[iA + VP4 + 8];
        const float4 kaB = cache4[iB],       kbB = cache4[iB + 8];
        const float4 vaB = cache4[iB + VP4], vbB = cache4[iB + VP4 + 8];

        float sA[GC], sB[GC];
#pragma unroll
        for (int g = 0; g < GC; g++) {
            sA[g] = dot8(qa[g], qb[g], kaA, kbA);
            sB[g] = dot8(qa[g], qb[g], kaB, kbB);
        }
#pragma unroll
        for (int off = 4; off >= 1; off >>= 1) {
#pragma unroll
            for (int g = 0; g < GC; g++) {
                sA[g] += __shfl_xor_sync(0xffffffffu, sA[g], off);
                sB[g] += __shfl_xor_sync(0xffffffffu, sB[g], off);
            }
        }
#pragma unroll
        for (int g = 0; g < GC; g++) {
            const float pA = vA ? __expf(sA[g]) : 0.f;
            const float pB = vB ? __expf(sB[g]) : 0.f;
            l[g] += pA + pB;
            acca[g].x += pA * vaA.x + pB * vaB.x;
            acca[g].y += pA * vaA.y + pB * vaB.y;
            acca[g].z += pA * vaA.z + pB * vaB.z;
            acca[g].w += pA * vaA.w + pB * vaB.w;
            accb[g].x += pA * vbA.x + pB * vbB.x;
            accb[g].y += pA * vbA.y + pB * vbB.y;
            accb[g].z += pA * vbA.z + pB * vbB.z;
            accb[g].w += pA * vbA.w + pB * vbB.w;
        }
    }

    // ---- t == pos handled once, by warp 0 / lane-group 0 of the owning split ----
    if (pos >= ts && pos < te && w == 0 && lane < 8) {
        const float4* kr = (const float4*)(k_last + ((size_t)(b * HK_ + hk)) * D_);
        const float4* vr = (const float4*)(v_last + ((size_t)(b * HK_ + hk)) * D_);
        const float4 ka = kr[e], kb = kr[e + 8];
        const float4 va = vr[e], vb = vr[e + 8];
        float s[GC];
#pragma unroll
        for (int g = 0; g < GC; g++) s[g] = dot8(qa[g], qb[g], ka, kb);
#pragma unroll
        for (int off = 4; off >= 1; off >>= 1) {
#pragma unroll
            for (int g = 0; g < GC; g++)
                s[g] += __shfl_xor_sync(0x000000ffu, s[g], off);
        }
#pragma unroll
        for (int g = 0; g < GC; g++) {
            const float p = __expf(s[g]);
            l[g] += p;
            acca[g].x += p * va.x; acca[g].y += p * va.y;
            acca[g].z += p * va.z; acca[g].w += p * va.w;
            accb[g].x += p * vb.x; accb[g].y += p * vb.y;
            accb[g].z += p * vb.z; accb[g].w += p * vb.w;
        }
    }

    // ---- merge the 4 lane-groups of each warp (pure sums, no max) ----
#pragma unroll
    for (int g = 0; g < GC; g++) {
#pragma unroll
        for (int off = 8; off <= 16; off <<= 1) {
            l[g]      += __shfl_xor_sync(0xffffffffu, l[g], off);
            acca[g].x += __shfl_xor_sync(0xffffffffu, acca[g].x, off);
            acca[g].y += __shfl_xor_sync(0xffffffffu, acca[g].y, off);
            acca[g].z += __shfl_xor_sync(0xffffffffu, acca[g].z, off);
            acca[g].w += __shfl_xor_sync(0xffffffffu, acca[g].w, off);
            accb[g].x += __shfl_xor_sync(0xffffffffu, accb[g].x, off);
            accb[g].y += __shfl_xor_sync(0xffffffffu, accb[g].y, off);
            accb[g].z += __shfl_xor_sync(0xffffffffu, accb[g].z, off);
            accb[g].w += __shfl_xor_sync(0xffffffffu, accb[g].w, off);
        }
    }

    // ---- cross-warp combine via smem ----
    __shared__ float sl_[NWARPS][GC];
    __shared__ float sa_[NWARPS][GC][D_];
    if (lane < 8) {
#pragma unroll
        for (int g = 0; g < GC; g++) {
            ((float4*)sa_[w][g])[e]     = acca[g];
            ((float4*)sa_[w][g])[e + 8] = accb[g];
        }
    }
    if (lane == 0) {
#pragma unroll
        for (int g = 0; g < GC; g++) sl_[w][g] = l[g];
    }
    __syncthreads();

    {
        const int g = tid >> 6;            // 0..1
        const int d = tid & 63;
        float Lt = 0.f, A = 0.f;
#pragma unroll
        for (int ww = 0; ww < NWARPS; ww++) {
            Lt += sl_[ww][g];
            A  += sa_[ww][g][d];
        }
        const int hq = hk * G_ + gh + g;
        const int idx = (b * HQ_ + hq) * NSPLIT + split;
        if (d == 0) g_l[idx] = Lt;
        g_acc[idx * D_ + d] = A;
    }

    // ---- split-KV finalization: last CTA per (b,hk2) reduces its 2 heads ----
    __shared__ int is_last;
    __threadfence();
    __syncthreads();
    if (tid == 0) {
        const int old = atomicAdd(&g_cnt[b * (HK_ * 2) + hk2], 1);
        is_last = (old == NSPLIT - 1);
    }
    __syncthreads();
    if (!is_last) return;
    __threadfence();

    {
        const int g = tid >> 6;
        const int d = tid & 63;
        const int hq = hk * G_ + gh + g;
        const int base = (b * HQ_ + hq) * NSPLIT;

        float Lt = __expf(sink[hq]);               // sink mass, denominator only
        float A  = 0.f;
#pragma unroll
        for (int s = 0; s < NSPLIT; s++) {
            Lt += g_l[base + s];
            A  += g_acc[(base + s) * D_ + d];
        }
        out[((size_t)(b * HQ_ + hq)) * D_ + d] = A / Lt;
    }
    if (tid == 0) g_cnt[b * (HK_ * 2) + hk2] = 0;  // reset for next graph replay
}

extern "C" void kernel_launch(void* const* d_in, const int* in_sizes, int n_in,
                              void* d_out, int out_size)
{
    const float* q_last     = (const float*)d_in[0];
    const float* k_last     = (const float*)d_in[1];
    const float* v_last     = (const float*)d_in[2];
    const float* cache      = (const float*)d_in[3];
    const int*   block_ids  = (const int*)d_in[4];
    const int*   start_pos  = (const int*)d_in[5];
    const float* sink       = (const float*)d_in[6];
    float*       out        = (float*)d_out;

    dim3 grid(B_, HK_ * 2, NSPLIT);
    attn_fused_kernel<<<grid, NTHREADS>>>(q_last, k_last, v_last, cache,
                                          block_ids, start_pos, sink, out);
}